// round 1
// baseline (speedup 1.0000x reference)
#include <cuda_runtime.h>
#include <cuda_bf16.h>
#include <math.h>

// ---------------------------------------------------------------------------
// Problem constants
// ---------------------------------------------------------------------------
#define BEV 320
#define NCELL (BEV*BEV)          // 102400
#define FEAT_H 128
#define FEAT_W 352
#define CCH 96
#define HID 64
#define NB 2

// ---------------------------------------------------------------------------
// Scratch (static device arrays; no allocation allowed)
// ---------------------------------------------------------------------------
__device__ float g_tfeat[NB * FEAT_H * FEAT_W * CCH];   // [B,H,W,C]
__device__ float g_fused[NB * CCH * NCELL];             // [B,C,320,320]
__device__ float g_mid  [NB * CCH * NCELL];
__device__ float g_K1[HID * HID];                       // dw2 @ sw1
__device__ float g_C1[3 * HID];                         // (db2+he[h]) @ sw1 + sb1

// ---------------------------------------------------------------------------
// Kernel 1: transpose image_feats [B,C,H,W] -> g_tfeat [B,H,W,C]
// ---------------------------------------------------------------------------
__global__ void transpose_kernel(const float* __restrict__ in)
{
    __shared__ float s[32][33];
    int tx = threadIdx.x, ty = threadIdx.y;
    int x0 = blockIdx.x * 32;        // 352/32 = 11 tiles
    int c0 = blockIdx.y * 32;        // 96/32 = 3 tiles
    int z  = blockIdx.z;             // b*128 + y
    int b = z >> 7, y = z & 127;
#pragma unroll
    for (int r = 0; r < 4; ++r) {
        int c = c0 + ty + r * 8;
        s[ty + r * 8][tx] = in[(((size_t)b * CCH + c) * FEAT_H + y) * FEAT_W + x0 + tx];
    }
    __syncthreads();
#pragma unroll
    for (int r = 0; r < 4; ++r) {
        int xo = ty + r * 8;
        g_tfeat[(((size_t)b * FEAT_H + y) * FEAT_W + x0 + xo) * CCH + c0 + tx] = s[tx][xo];
    }
}

// ---------------------------------------------------------------------------
// Kernel 2: fold depth-MLP into score-MLP hidden layer.
//   K1[k][j] = sum_c dw2[k][c] * sw1[c][j]
//   C1[h][j] = sb1[j] + sum_c (db2[c] + he[h][c]) * sw1[c][j]
// ---------------------------------------------------------------------------
__global__ void prep_kernel(const float* __restrict__ dw2, const float* __restrict__ sw1,
                            const float* __restrict__ db2, const float* __restrict__ he,
                            const float* __restrict__ sb1)
{
    int j = threadIdx.x;
    int r = blockIdx.x;
    if (r < HID) {
        float a = 0.f;
        for (int c = 0; c < CCH; ++c) a = fmaf(dw2[r * CCH + c], sw1[c * HID + j], a);
        g_K1[r * HID + j] = a;
    } else {
        int h = r - HID;
        float a = sb1[j];
        for (int c = 0; c < CCH; ++c) a = fmaf(db2[c] + he[h * CCH + c], sw1[c * HID + j], a);
        g_C1[h * HID + j] = a;
    }
}

// ---------------------------------------------------------------------------
// Kernel 3: BEV lift. Persistent blocks of 256 threads (8 warps).
// Each tile = 32 consecutive x-cells of one BEV row; warp-per-cell (4 cells/warp),
// lane owns channels {lane, lane+32, lane+64}.
// ---------------------------------------------------------------------------
__global__ void __launch_bounds__(256)
lift_kernel(const float* __restrict__ l2i, const float* __restrict__ sw1,
            const float* __restrict__ dw1, const float* __restrict__ db1,
            const float* __restrict__ sw2, const float* __restrict__ sb2p)
{
    extern __shared__ float sm[];
    float2* s_sw1 = (float2*)sm;              // 96*32 float2  (sw1[c][2l],sw1[c][2l+1])
    float2* s_K1  = s_sw1 + CCH * 32;         // 64*32 float2
    float*  s_C1  = (float*)(s_K1 + HID * 32);// 192
    float*  s_dw1 = s_C1 + 192;               // 64
    float*  s_db1 = s_dw1 + 64;               // 64
    float*  s_sw2 = s_db1 + 64;               // 64
    float*  s_samp = s_sw2 + 64;              // 8 warps * 96
    float*  s_fused = s_samp + 8 * CCH;       // 32 cells * 97 (padded)

    int tid = threadIdx.x;
    int w = tid >> 5, lane = tid & 31;
    int j0 = 2 * lane;

    for (int i = tid; i < CCH * 32; i += 256) s_sw1[i] = ((const float2*)sw1)[i];
    for (int i = tid; i < HID * 32; i += 256) s_K1[i] = ((const float2*)g_K1)[i];
    if (tid < 192) s_C1[tid] = g_C1[tid];
    if (tid < 64) { s_dw1[tid] = dw1[tid]; s_db1[tid] = db1[tid]; s_sw2[tid] = sw2[tid]; }
    __syncthreads();
    float sb2 = *sb2p;

    const int NTILES = NB * NCELL / 32;  // 6400
    for (int tile = blockIdx.x; tile < NTILES; tile += gridDim.x) {
        int N0 = tile * 32;
        int b = (N0 >= NCELL) ? 1 : 0;
        int n0 = N0 - b * NCELL;
        int y = n0 / BEV;
        int x0 = n0 - y * BEV;

        const float* M = l2i + b * 16;
        float M00 = M[0], M01 = M[1], M02 = M[2],  M03 = M[3];
        float M10 = M[4], M11 = M[5], M12 = M[6],  M13 = M[7];
        float M20 = M[8], M21 = M[9], M22 = M[10], M23 = M[11];

        float py = ((float)y + 0.5f) / 320.0f * 102.4f - 51.2f;

        for (int cc = 0; cc < 4; ++cc) {
            int cj = w + cc * 8;
            int x = x0 + cj;
            float px = ((float)x + 0.5f) / 320.0f * 102.4f - 51.2f;
            float b0 = M00 * px + M01 * py + M03;
            float b1 = M10 * px + M11 * py + M13;
            float b2 = M20 * px + M21 * py + M23;

            float lg[3];
            float sA0[3], sA1[3], sA2[3];

#pragma unroll
            for (int h = 0; h < 3; ++h) {
                float fh = (float)h;
                float p0 = b0 + fh * M02;
                float p1 = b1 + fh * M12;
                float dep = b2 + fh * M22;
                float dn = fmaxf(dep, 1e-5f);
                float u = p0 / dn, v = p1 / dn;
                float gx = u / 351.0f * 2.0f - 1.0f;
                float gy = v / 127.0f * 2.0f - 1.0f;
                bool valid = (dep > 1e-3f) && (fabsf(gx) <= 1.0f) && (fabsf(gy) <= 1.0f);

                float s0 = 0.f, s1 = 0.f, s2 = 0.f;
                float logit = -INFINITY;

                if (valid) {   // uniform across the warp (per-cell predicate)
                    float xs = (gx + 1.0f) * 0.5f * 351.0f;
                    float ys = (gy + 1.0f) * 0.5f * 127.0f;
                    float xf = floorf(xs), yf = floorf(ys);
                    float wx = xs - xf, wy = ys - yf;
                    int ix = (int)xf, iy = (int)yf;
                    int ix1 = ix + 1, iy1 = iy + 1;
                    float w00 = (1.f - wx) * (1.f - wy);
                    float w10 = wx * (1.f - wy);
                    float w01 = (1.f - wx) * wy;
                    float w11 = wx * wy;
                    if (ix1 > 351) { ix1 = 351; w10 = 0.f; w11 = 0.f; }
                    if (iy1 > 127) { iy1 = 127; w01 = 0.f; w11 = 0.f; }

                    int rowA = (b * FEAT_H + iy) * FEAT_W;
                    int rowB = (b * FEAT_H + iy1) * FEAT_W;
                    int o00 = (rowA + ix) * CCH + lane;
                    int o10 = (rowA + ix1) * CCH + lane;
                    int o01 = (rowB + ix) * CCH + lane;
                    int o11 = (rowB + ix1) * CCH + lane;
#pragma unroll
                    for (int k = 0; k < 3; ++k) {
                        float A = g_tfeat[o00 + 32 * k];
                        float Bv = g_tfeat[o10 + 32 * k];
                        float Cv = g_tfeat[o01 + 32 * k];
                        float Dv = g_tfeat[o11 + 32 * k];
                        float sv = fmaf(w00, A, fmaf(w10, Bv, fmaf(w01, Cv, w11 * Dv)));
                        if (k == 0) s0 = sv; else if (k == 1) s1 = sv; else s2 = sv;
                    }
                    s_samp[w * CCH + lane]      = s0;
                    s_samp[w * CCH + lane + 32] = s1;
                    s_samp[w * CCH + lane + 64] = s2;
                    __syncwarp();

                    float d = log1pf(fmaxf(dep, 1e-3f));
                    float a0 = s_C1[h * HID + j0];
                    float a1 = s_C1[h * HID + j0 + 1];
#pragma unroll 8
                    for (int k = 0; k < HID; ++k) {
                        float hv = fmaxf(fmaf(d, s_dw1[k], s_db1[k]), 0.f);
                        float2 kk = s_K1[k * 32 + lane];
                        a0 = fmaf(hv, kk.x, a0);
                        a1 = fmaf(hv, kk.y, a1);
                    }
#pragma unroll 8
                    for (int c = 0; c < CCH; ++c) {
                        float t = s_samp[w * CCH + c];
                        float2 ww = s_sw1[c * 32 + lane];
                        a0 = fmaf(t, ww.x, a0);
                        a1 = fmaf(t, ww.y, a1);
                    }
                    a0 = fmaxf(a0, 0.f);
                    a1 = fmaxf(a1, 0.f);
                    float part = a0 * s_sw2[j0] + a1 * s_sw2[j0 + 1];
#pragma unroll
                    for (int off = 16; off > 0; off >>= 1)
                        part += __shfl_xor_sync(0xffffffffu, part, off);
                    logit = part + sb2;
                    __syncwarp();
                }
                lg[h] = logit;
                sA0[h] = s0; sA1[h] = s1; sA2[h] = s2;
            }

            // softmax over valid heights
            float m = fmaxf(fmaxf(lg[0], lg[1]), lg[2]);
            float e0 = 0.f, e1 = 0.f, e2 = 0.f;
            if (m > -1e30f) {
                e0 = expf(lg[0] - m);
                e1 = expf(lg[1] - m);
                e2 = expf(lg[2] - m);
                float inv = 1.0f / (e0 + e1 + e2);
                e0 *= inv; e1 *= inv; e2 *= inv;
            }
            float f0 = sA0[0] * e0 + sA0[1] * e1 + sA0[2] * e2;
            float f1 = sA1[0] * e0 + sA1[1] * e1 + sA1[2] * e2;
            float f2 = sA2[0] * e0 + sA2[1] * e1 + sA2[2] * e2;
            s_fused[cj * 97 + lane]      = f0;
            s_fused[cj * 97 + lane + 32] = f1;
            s_fused[cj * 97 + lane + 64] = f2;
        }
        __syncthreads();
        // coalesced writeback: [C][x-run of 32]
        for (int i = tid; i < CCH * 32; i += 256) {
            int c = i >> 5, xo = i & 31;
            g_fused[(size_t)b * (CCH * NCELL) + (size_t)c * NCELL + n0 + xo] =
                s_fused[xo * 97 + c];
        }
        __syncthreads();
    }
}

// ---------------------------------------------------------------------------
// Kernel 4: direct 3x3 conv + BN + ReLU with packed f32x2 FMA.
// Block: (32,8) threads. Tile: 64(x) x 32(y) outputs, 4 output channels.
// Each thread: pixel-pair (x0+2tx, x0+2tx+1) at 4 y rows -> 16 f32x2 accumulators.
// ---------------------------------------------------------------------------
__device__ __forceinline__ unsigned long long ffma2(unsigned long long a,
                                                    unsigned long long b,
                                                    unsigned long long c)
{
    unsigned long long d;
    asm("fma.rn.f32x2 %0, %1, %2, %3;" : "=l"(d) : "l"(a), "l"(b), "l"(c));
    return d;
}

template <int PHASE>
__global__ void __launch_bounds__(256)
conv_kernel(const float* __restrict__ wts,
            const float* __restrict__ gg, const float* __restrict__ bb_,
            const float* __restrict__ mm, const float* __restrict__ vv,
            float* __restrict__ out_ext)
{
    const float* __restrict__ in = (PHASE == 0) ? g_fused : g_mid;
    float* __restrict__ out = (PHASE == 0) ? g_mid : out_ext;

    __shared__ __align__(16) float s_in[34 * 66];
    __shared__ float2 s_w[4 * 96 * 9];

    int tx = threadIdx.x, ty = threadIdx.y;
    int tid = ty * 32 + tx;
    int ocb = blockIdx.z % 24;
    int b = blockIdx.z / 24;
    int oc0 = ocb * 4;
    int x0 = blockIdx.x * 64;
    int y0 = blockIdx.y * 32;

    // duplicate weights into float2 pairs once per block
    for (int i = tid; i < 4 * 96 * 9; i += 256) {
        int oc = i / 864;
        int rem = i - oc * 864;
        float wv = wts[(size_t)(oc0 + oc) * 864 + rem];
        s_w[i] = make_float2(wv, wv);
    }
    float al[4], be[4];
#pragma unroll
    for (int oc = 0; oc < 4; ++oc) {
        float a = gg[oc0 + oc] * rsqrtf(vv[oc0 + oc] + 1e-3f);
        al[oc] = a;
        be[oc] = bb_[oc0 + oc] - mm[oc0 + oc] * a;
    }

    unsigned long long acc[16];
#pragma unroll
    for (int i = 0; i < 16; ++i) acc[i] = 0ULL;

    for (int ic = 0; ic < CCH; ++ic) {
        __syncthreads();
        for (int i = tid; i < 34 * 66; i += 256) {
            int r = i / 66;
            int col = i - r * 66;
            int gy = y0 - 1 + r;
            int gx = x0 - 1 + col;
            float vval = 0.f;
            if ((unsigned)gy < 320u && (unsigned)gx < 320u)
                vval = in[(((size_t)b * CCH + ic) * BEV + gy) * BEV + gx];
            s_in[i] = vval;
        }
        __syncthreads();

#pragma unroll
        for (int ky = 0; ky < 3; ++ky) {
            unsigned long long wd[12];
#pragma unroll
            for (int oc = 0; oc < 4; ++oc)
#pragma unroll
                for (int kx = 0; kx < 3; ++kx)
                    wd[oc * 3 + kx] = *reinterpret_cast<const unsigned long long*>(
                        &s_w[oc * 864 + ic * 9 + ky * 3 + kx]);
#pragma unroll
            for (int pp = 0; pp < 4; ++pp) {
                int ry = ty + pp * 8 + ky;
                const unsigned long long* row =
                    reinterpret_cast<const unsigned long long*>(s_in + ry * 66);
                unsigned long long W0 = row[tx];       // cols 2tx, 2tx+1
                unsigned long long W1 = row[tx + 1];   // cols 2tx+2, 2tx+3
                unsigned long long P1 = (W0 >> 32) | (W1 << 32);
#pragma unroll
                for (int oc = 0; oc < 4; ++oc) {
                    unsigned long long a = acc[pp * 4 + oc];
                    a = ffma2(W0, wd[oc * 3 + 0], a);
                    a = ffma2(P1, wd[oc * 3 + 1], a);
                    a = ffma2(W1, wd[oc * 3 + 2], a);
                    acc[pp * 4 + oc] = a;
                }
            }
        }
    }

#pragma unroll
    for (int pp = 0; pp < 4; ++pp) {
        int yy = y0 + ty + pp * 8;
#pragma unroll
        for (int oc = 0; oc < 4; ++oc) {
            unsigned long long a = acc[pp * 4 + oc];
            float lo = __uint_as_float((unsigned)(a & 0xffffffffULL));
            float hi = __uint_as_float((unsigned)(a >> 32));
            float2 o;
            o.x = fmaxf(fmaf(lo, al[oc], be[oc]), 0.f);
            o.y = fmaxf(fmaf(hi, al[oc], be[oc]), 0.f);
            *reinterpret_cast<float2*>(
                &out[(((size_t)b * CCH + oc0 + oc) * BEV + yy) * BEV + x0 + 2 * tx]) = o;
        }
    }
}

// ---------------------------------------------------------------------------
// Launch
// ---------------------------------------------------------------------------
extern "C" void kernel_launch(void* const* d_in, const int* in_sizes, int n_in,
                              void* d_out, int out_size)
{
    const float* feats = (const float*)d_in[0];
    const float* l2i   = (const float*)d_in[1];
    const float* he    = (const float*)d_in[2];
    const float* dw1   = (const float*)d_in[3];
    const float* db1   = (const float*)d_in[4];
    const float* dw2   = (const float*)d_in[5];
    const float* db2   = (const float*)d_in[6];
    const float* sw1   = (const float*)d_in[7];
    const float* sb1   = (const float*)d_in[8];
    const float* sw2   = (const float*)d_in[9];
    const float* sb2   = (const float*)d_in[10];
    const float* c1w   = (const float*)d_in[11];
    const float* b1g   = (const float*)d_in[12];
    const float* b1b   = (const float*)d_in[13];
    const float* b1m   = (const float*)d_in[14];
    const float* b1v   = (const float*)d_in[15];
    const float* c2w   = (const float*)d_in[16];
    const float* b2g   = (const float*)d_in[17];
    const float* b2b   = (const float*)d_in[18];
    const float* b2m   = (const float*)d_in[19];
    const float* b2v   = (const float*)d_in[20];
    float* out = (float*)d_out;

    // 1. transpose features to channel-last for coalesced bilinear gathers
    transpose_kernel<<<dim3(11, 3, NB * FEAT_H), dim3(32, 8)>>>(feats);

    // 2. fold depth-MLP into hidden layer
    prep_kernel<<<HID + 3, HID>>>(dw2, sw1, db2, he, sb1);

    // 3. lift (persistent blocks, dynamic smem ~57KB)
    size_t lsm = (size_t)(CCH * 32) * 8 + (size_t)(HID * 32) * 8 +
                 (192 + 64 + 64 + 64) * 4 + 8 * CCH * 4 + 32 * 97 * 4;
    cudaFuncSetAttribute(lift_kernel, cudaFuncAttributeMaxDynamicSharedMemorySize, (int)lsm);
    lift_kernel<<<444, 256, lsm>>>(l2i, sw1, dw1, db1, sw2, sb2);

    // 4. conv1 + BN + ReLU  (g_fused -> g_mid)
    conv_kernel<0><<<dim3(5, 10, 48), dim3(32, 8)>>>(c1w, b1g, b1b, b1m, b1v, out);
    // 5. conv2 + BN + ReLU  (g_mid -> d_out)
    conv_kernel<1><<<dim3(5, 10, 48), dim3(32, 8)>>>(c2w, b2g, b2b, b2m, b2v, out);
}

// round 2
// speedup vs baseline: 1.3070x; 1.3070x over previous
#include <cuda_runtime.h>
#include <cuda_bf16.h>
#include <math.h>

// ---------------------------------------------------------------------------
// Problem constants
// ---------------------------------------------------------------------------
#define BEV 320
#define NCELL (BEV*BEV)          // 102400
#define FEAT_H 128
#define FEAT_W 352
#define CCH 96
#define HID 64
#define NB 2

// Padded conv activation layout: [C][322][328], halo of zeros around 320x320.
#define PH 322
#define PW 328
#define PLANE (PH*PW)

// ---------------------------------------------------------------------------
// Scratch (static device arrays; no allocation allowed)
// ---------------------------------------------------------------------------
__device__ float g_tfeat[NB * FEAT_H * FEAT_W * CCH];   // [B,H,W,C]
__device__ float g_fused[NB * CCH * PLANE];             // padded [B,C,322,328]
__device__ float g_mid  [NB * CCH * PLANE];             // padded
__device__ float g_K1[HID * HID];                       // dw2 @ sw1
__device__ float g_C1[3 * HID];                         // (db2+he[h]) @ sw1 + sb1

// ---------------------------------------------------------------------------
// Kernel 0: zero the halo border of g_fused and g_mid (every launch).
// ---------------------------------------------------------------------------
__global__ void border_kernel()
{
    int p = blockIdx.x;                      // 0..383
    float* base = (p < NB * CCH ? g_fused : g_mid) + (size_t)(p % (NB * CCH)) * PLANE;
    int tid = threadIdx.x;
    for (int i = tid; i < PW; i += 256) {
        base[i] = 0.f;
        base[(PH - 1) * PW + i] = 0.f;
    }
    for (int i = tid; i < PH; i += 256) {
        base[i * PW] = 0.f;
        base[i * PW + 321] = 0.f;
    }
}

// ---------------------------------------------------------------------------
// Kernel 1: transpose image_feats [B,C,H,W] -> g_tfeat [B,H,W,C]
// ---------------------------------------------------------------------------
__global__ void transpose_kernel(const float* __restrict__ in)
{
    __shared__ float s[32][33];
    int tx = threadIdx.x, ty = threadIdx.y;
    int x0 = blockIdx.x * 32;
    int c0 = blockIdx.y * 32;
    int z  = blockIdx.z;
    int b = z >> 7, y = z & 127;
#pragma unroll
    for (int r = 0; r < 4; ++r) {
        int c = c0 + ty + r * 8;
        s[ty + r * 8][tx] = in[(((size_t)b * CCH + c) * FEAT_H + y) * FEAT_W + x0 + tx];
    }
    __syncthreads();
#pragma unroll
    for (int r = 0; r < 4; ++r) {
        int xo = ty + r * 8;
        g_tfeat[(((size_t)b * FEAT_H + y) * FEAT_W + x0 + xo) * CCH + c0 + tx] = s[tx][xo];
    }
}

// ---------------------------------------------------------------------------
// Kernel 2: fold depth-MLP into score-MLP hidden layer.
// ---------------------------------------------------------------------------
__global__ void prep_kernel(const float* __restrict__ dw2, const float* __restrict__ sw1,
                            const float* __restrict__ db2, const float* __restrict__ he,
                            const float* __restrict__ sb1)
{
    int j = threadIdx.x;
    int r = blockIdx.x;
    if (r < HID) {
        float a = 0.f;
        for (int c = 0; c < CCH; ++c) a = fmaf(dw2[r * CCH + c], sw1[c * HID + j], a);
        g_K1[r * HID + j] = a;
    } else {
        int h = r - HID;
        float a = sb1[j];
        for (int c = 0; c < CCH; ++c) a = fmaf(db2[c] + he[h * CCH + c], sw1[c * HID + j], a);
        g_C1[h * HID + j] = a;
    }
}

// ---------------------------------------------------------------------------
// Kernel 3: BEV lift (unchanged except padded writeback).
// ---------------------------------------------------------------------------
__global__ void __launch_bounds__(256)
lift_kernel(const float* __restrict__ l2i, const float* __restrict__ sw1,
            const float* __restrict__ dw1, const float* __restrict__ db1,
            const float* __restrict__ sw2, const float* __restrict__ sb2p)
{
    extern __shared__ float sm[];
    float2* s_sw1 = (float2*)sm;
    float2* s_K1  = s_sw1 + CCH * 32;
    float*  s_C1  = (float*)(s_K1 + HID * 32);
    float*  s_dw1 = s_C1 + 192;
    float*  s_db1 = s_dw1 + 64;
    float*  s_sw2 = s_db1 + 64;
    float*  s_samp = s_sw2 + 64;
    float*  s_fused = s_samp + 8 * CCH;

    int tid = threadIdx.x;
    int w = tid >> 5, lane = tid & 31;
    int j0 = 2 * lane;

    for (int i = tid; i < CCH * 32; i += 256) s_sw1[i] = ((const float2*)sw1)[i];
    for (int i = tid; i < HID * 32; i += 256) s_K1[i] = ((const float2*)g_K1)[i];
    if (tid < 192) s_C1[tid] = g_C1[tid];
    if (tid < 64) { s_dw1[tid] = dw1[tid]; s_db1[tid] = db1[tid]; s_sw2[tid] = sw2[tid]; }
    __syncthreads();
    float sb2 = *sb2p;

    const int NTILES = NB * NCELL / 32;
    for (int tile = blockIdx.x; tile < NTILES; tile += gridDim.x) {
        int N0 = tile * 32;
        int b = (N0 >= NCELL) ? 1 : 0;
        int n0 = N0 - b * NCELL;
        int y = n0 / BEV;
        int x0 = n0 - y * BEV;

        const float* M = l2i + b * 16;
        float M00 = M[0], M01 = M[1], M02 = M[2],  M03 = M[3];
        float M10 = M[4], M11 = M[5], M12 = M[6],  M13 = M[7];
        float M20 = M[8], M21 = M[9], M22 = M[10], M23 = M[11];

        float py = ((float)y + 0.5f) / 320.0f * 102.4f - 51.2f;

        for (int cc = 0; cc < 4; ++cc) {
            int cj = w + cc * 8;
            int x = x0 + cj;
            float px = ((float)x + 0.5f) / 320.0f * 102.4f - 51.2f;
            float b0 = M00 * px + M01 * py + M03;
            float b1 = M10 * px + M11 * py + M13;
            float b2 = M20 * px + M21 * py + M23;

            float lg[3];
            float sA0[3], sA1[3], sA2[3];

#pragma unroll
            for (int h = 0; h < 3; ++h) {
                float fh = (float)h;
                float p0 = b0 + fh * M02;
                float p1 = b1 + fh * M12;
                float dep = b2 + fh * M22;
                float dn = fmaxf(dep, 1e-5f);
                float u = p0 / dn, v = p1 / dn;
                float gx = u / 351.0f * 2.0f - 1.0f;
                float gy = v / 127.0f * 2.0f - 1.0f;
                bool valid = (dep > 1e-3f) && (fabsf(gx) <= 1.0f) && (fabsf(gy) <= 1.0f);

                float s0 = 0.f, s1 = 0.f, s2 = 0.f;
                float logit = -INFINITY;

                if (valid) {
                    float xs = (gx + 1.0f) * 0.5f * 351.0f;
                    float ys = (gy + 1.0f) * 0.5f * 127.0f;
                    float xf = floorf(xs), yf = floorf(ys);
                    float wx = xs - xf, wy = ys - yf;
                    int ix = (int)xf, iy = (int)yf;
                    int ix1 = ix + 1, iy1 = iy + 1;
                    float w00 = (1.f - wx) * (1.f - wy);
                    float w10 = wx * (1.f - wy);
                    float w01 = (1.f - wx) * wy;
                    float w11 = wx * wy;
                    if (ix1 > 351) { ix1 = 351; w10 = 0.f; w11 = 0.f; }
                    if (iy1 > 127) { iy1 = 127; w01 = 0.f; w11 = 0.f; }

                    int rowA = (b * FEAT_H + iy) * FEAT_W;
                    int rowB = (b * FEAT_H + iy1) * FEAT_W;
                    int o00 = (rowA + ix) * CCH + lane;
                    int o10 = (rowA + ix1) * CCH + lane;
                    int o01 = (rowB + ix) * CCH + lane;
                    int o11 = (rowB + ix1) * CCH + lane;
#pragma unroll
                    for (int k = 0; k < 3; ++k) {
                        float A = g_tfeat[o00 + 32 * k];
                        float Bv = g_tfeat[o10 + 32 * k];
                        float Cv = g_tfeat[o01 + 32 * k];
                        float Dv = g_tfeat[o11 + 32 * k];
                        float sv = fmaf(w00, A, fmaf(w10, Bv, fmaf(w01, Cv, w11 * Dv)));
                        if (k == 0) s0 = sv; else if (k == 1) s1 = sv; else s2 = sv;
                    }
                    s_samp[w * CCH + lane]      = s0;
                    s_samp[w * CCH + lane + 32] = s1;
                    s_samp[w * CCH + lane + 64] = s2;
                    __syncwarp();

                    float d = log1pf(fmaxf(dep, 1e-3f));
                    float a0 = s_C1[h * HID + j0];
                    float a1 = s_C1[h * HID + j0 + 1];
#pragma unroll 8
                    for (int k = 0; k < HID; ++k) {
                        float hv = fmaxf(fmaf(d, s_dw1[k], s_db1[k]), 0.f);
                        float2 kk = s_K1[k * 32 + lane];
                        a0 = fmaf(hv, kk.x, a0);
                        a1 = fmaf(hv, kk.y, a1);
                    }
#pragma unroll 8
                    for (int c = 0; c < CCH; ++c) {
                        float t = s_samp[w * CCH + c];
                        float2 ww = s_sw1[c * 32 + lane];
                        a0 = fmaf(t, ww.x, a0);
                        a1 = fmaf(t, ww.y, a1);
                    }
                    a0 = fmaxf(a0, 0.f);
                    a1 = fmaxf(a1, 0.f);
                    float part = a0 * s_sw2[j0] + a1 * s_sw2[j0 + 1];
#pragma unroll
                    for (int off = 16; off > 0; off >>= 1)
                        part += __shfl_xor_sync(0xffffffffu, part, off);
                    logit = part + sb2;
                    __syncwarp();
                }
                lg[h] = logit;
                sA0[h] = s0; sA1[h] = s1; sA2[h] = s2;
            }

            float m = fmaxf(fmaxf(lg[0], lg[1]), lg[2]);
            float e0 = 0.f, e1 = 0.f, e2 = 0.f;
            if (m > -1e30f) {
                e0 = expf(lg[0] - m);
                e1 = expf(lg[1] - m);
                e2 = expf(lg[2] - m);
                float inv = 1.0f / (e0 + e1 + e2);
                e0 *= inv; e1 *= inv; e2 *= inv;
            }
            float f0 = sA0[0] * e0 + sA0[1] * e1 + sA0[2] * e2;
            float f1 = sA1[0] * e0 + sA1[1] * e1 + sA1[2] * e2;
            float f2 = sA2[0] * e0 + sA2[1] * e1 + sA2[2] * e2;
            s_fused[cj * 97 + lane]      = f0;
            s_fused[cj * 97 + lane + 32] = f1;
            s_fused[cj * 97 + lane + 64] = f2;
        }
        __syncthreads();
        // writeback into padded layout
        for (int i = tid; i < CCH * 32; i += 256) {
            int c = i >> 5, xo = i & 31;
            g_fused[((size_t)(b * CCH + c) * PH + (y + 1)) * PW + x0 + xo + 1] =
                s_fused[xo * 97 + c];
        }
        __syncthreads();
    }
}

// ---------------------------------------------------------------------------
// Kernel 4: 3x3 conv + BN + ReLU, packed f32x2 FMA.
// Block (32,8): tile = 64(x) x 32(y) x 8(oc). Thread: 2 px x 4 rows x 8 oc.
// Padded input (no bounds checks), ICB=4 channel staging, double-buffered
// cp.async, weights restaged as [ic][ky][kx][oc] duplicated f32x2.
// ---------------------------------------------------------------------------
__device__ __forceinline__ unsigned long long ffma2(unsigned long long a,
                                                    unsigned long long b,
                                                    unsigned long long c)
{
    unsigned long long d;
    asm("fma.rn.f32x2 %0, %1, %2, %3;" : "=l"(d) : "l"(a), "l"(b), "l"(c));
    return d;
}

__device__ __forceinline__ void cpa16(void* dst, const void* src)
{
    unsigned d = (unsigned)__cvta_generic_to_shared(dst);
    asm volatile("cp.async.ca.shared.global [%0], [%1], 16;\n" :: "r"(d), "l"(src));
}

#define ICB 4
#define NROUND (CCH / ICB)       // 24
#define SW_ULL (CCH * 9 * 8)     // 6912 f32x2 weights
#define SIN_ROW 68               // padded smem row (floats), 272B = 17x16B
#define SIN_CH  (34 * SIN_ROW)   // 2312 floats per channel
#define SIN_BUF (ICB * SIN_CH)   // per buffer

template <int PHASE>
__global__ void __launch_bounds__(256)
conv_kernel(const float* __restrict__ wts,
            const float* __restrict__ gg, const float* __restrict__ bb_,
            const float* __restrict__ mm, const float* __restrict__ vv,
            float* __restrict__ out_ext)
{
    const float* __restrict__ in = (PHASE == 0) ? g_fused : g_mid;

    extern __shared__ float smem[];
    unsigned long long* s_w = (unsigned long long*)smem;   // 55296 B
    float* s_in = smem + SW_ULL * 2;                       // 2*SIN_BUF floats

    int tx = threadIdx.x, ty = threadIdx.y;
    int tid = ty * 32 + tx;
    int z = blockIdx.z;
    int b = z / 12, ocb = z - b * 12;
    int oc0 = ocb * 8;
    int x0 = blockIdx.x * 64;
    int y0 = blockIdx.y * 32;

    // stage weights: s_w[(ic*9 + ky*3 + kx)*8 + oc] = dup(w[oc0+oc][ic][ky][kx])
    for (int i = tid; i < SW_ULL; i += 256) {
        int oc = i & 7;
        int r = i >> 3;                      // ic*9 + k9
        unsigned u = __float_as_uint(wts[(size_t)(oc0 + oc) * 864 + r]);
        s_w[i] = (unsigned long long)u | ((unsigned long long)u << 32);
    }

    float al[8], be[8];
#pragma unroll
    for (int oc = 0; oc < 8; ++oc) {
        float a = gg[oc0 + oc] * rsqrtf(vv[oc0 + oc] + 1e-3f);
        al[oc] = a;
        be[oc] = bb_[oc0 + oc] - mm[oc0 + oc] * a;
    }

    const float* src_base = in + (size_t)b * CCH * PLANE + (size_t)y0 * PW + x0;

    // prologue: stage round 0 into buf 0
    {
        for (int idx = tid; idx < ICB * 34 * 17; idx += 256) {
            int ic = idx / (34 * 17);
            int rem = idx - ic * (34 * 17);
            int row = rem / 17;
            int ch = rem - row * 17;
            cpa16(s_in + (ic * 34 + row) * SIN_ROW + ch * 4,
                  src_base + (size_t)ic * PLANE + row * PW + ch * 4);
        }
        asm volatile("cp.async.commit_group;\n");
    }

    unsigned long long acc[32];
#pragma unroll
    for (int i = 0; i < 32; ++i) acc[i] = 0ULL;

    for (int r = 0; r < NROUND; ++r) {
        int buf = r & 1;
        if (r + 1 < NROUND) {
            const float* sb = src_base + (size_t)(r + 1) * ICB * PLANE;
            float* db = s_in + ((r + 1) & 1) * SIN_BUF;
            for (int idx = tid; idx < ICB * 34 * 17; idx += 256) {
                int ic = idx / (34 * 17);
                int rem = idx - ic * (34 * 17);
                int row = rem / 17;
                int ch = rem - row * 17;
                cpa16(db + (ic * 34 + row) * SIN_ROW + ch * 4,
                      sb + (size_t)ic * PLANE + row * PW + ch * 4);
            }
            asm volatile("cp.async.commit_group;\n");
            asm volatile("cp.async.wait_group 1;\n");
        } else {
            asm volatile("cp.async.wait_group 0;\n");
        }
        __syncthreads();

        for (int icb = 0; icb < ICB; ++icb) {
            const float* pin = s_in + buf * SIN_BUF + icb * SIN_CH;
            const unsigned long long* pw = s_w + (size_t)(r * ICB + icb) * 72;
#pragma unroll
            for (int ky = 0; ky < 3; ++ky) {
                unsigned long long wd[24];
#pragma unroll
                for (int j = 0; j < 12; ++j) {
                    ulonglong2 t = ((const ulonglong2*)(pw + ky * 24))[j];
                    wd[2 * j] = t.x;
                    wd[2 * j + 1] = t.y;
                }
#pragma unroll
                for (int pp = 0; pp < 4; ++pp) {
                    const float* prow = pin + (ty + 8 * pp + ky) * SIN_ROW + 2 * tx;
                    unsigned long long W0 = *(const unsigned long long*)prow;
                    unsigned long long W1 = *(const unsigned long long*)(prow + 2);
                    unsigned long long P1 = (W0 >> 32) | (W1 << 32);
#pragma unroll
                    for (int oc = 0; oc < 8; ++oc) {
                        unsigned long long a = acc[pp * 8 + oc];
                        a = ffma2(W0, wd[oc], a);
                        a = ffma2(P1, wd[8 + oc], a);
                        a = ffma2(W1, wd[16 + oc], a);
                        acc[pp * 8 + oc] = a;
                    }
                }
            }
        }
        __syncthreads();
    }

    // epilogue: BN + ReLU + store
#pragma unroll
    for (int pp = 0; pp < 4; ++pp) {
        int yy = y0 + ty + 8 * pp;
#pragma unroll
        for (int oc = 0; oc < 8; ++oc) {
            unsigned long long a = acc[pp * 8 + oc];
            float lo = __uint_as_float((unsigned)(a & 0xffffffffULL));
            float hi = __uint_as_float((unsigned)(a >> 32));
            lo = fmaxf(fmaf(lo, al[oc], be[oc]), 0.f);
            hi = fmaxf(fmaf(hi, al[oc], be[oc]), 0.f);
            if (PHASE == 0) {
                size_t o = ((size_t)(b * CCH + oc0 + oc) * PH + yy + 1) * PW + x0 + 2 * tx + 1;
                g_mid[o] = lo;
                g_mid[o + 1] = hi;
            } else {
                float2 o2 = make_float2(lo, hi);
                *reinterpret_cast<float2*>(
                    &out_ext[((size_t)(b * CCH + oc0 + oc) * BEV + yy) * BEV + x0 + 2 * tx]) = o2;
            }
        }
    }
}

// ---------------------------------------------------------------------------
// Launch
// ---------------------------------------------------------------------------
extern "C" void kernel_launch(void* const* d_in, const int* in_sizes, int n_in,
                              void* d_out, int out_size)
{
    const float* feats = (const float*)d_in[0];
    const float* l2i   = (const float*)d_in[1];
    const float* he    = (const float*)d_in[2];
    const float* dw1   = (const float*)d_in[3];
    const float* db1   = (const float*)d_in[4];
    const float* dw2   = (const float*)d_in[5];
    const float* db2   = (const float*)d_in[6];
    const float* sw1   = (const float*)d_in[7];
    const float* sb1   = (const float*)d_in[8];
    const float* sw2   = (const float*)d_in[9];
    const float* sb2   = (const float*)d_in[10];
    const float* c1w   = (const float*)d_in[11];
    const float* b1g   = (const float*)d_in[12];
    const float* b1b   = (const float*)d_in[13];
    const float* b1m   = (const float*)d_in[14];
    const float* b1v   = (const float*)d_in[15];
    const float* c2w   = (const float*)d_in[16];
    const float* b2g   = (const float*)d_in[17];
    const float* b2b   = (const float*)d_in[18];
    const float* b2m   = (const float*)d_in[19];
    const float* b2v   = (const float*)d_in[20];
    float* out = (float*)d_out;

    border_kernel<<<2 * NB * CCH, 256>>>();
    transpose_kernel<<<dim3(11, 3, NB * FEAT_H), dim3(32, 8)>>>(feats);
    prep_kernel<<<HID + 3, HID>>>(dw2, sw1, db2, he, sb1);

    size_t lsm = (size_t)(CCH * 32) * 8 + (size_t)(HID * 32) * 8 +
                 (192 + 64 + 64 + 64) * 4 + 8 * CCH * 4 + 32 * 97 * 4;
    cudaFuncSetAttribute(lift_kernel, cudaFuncAttributeMaxDynamicSharedMemorySize, (int)lsm);
    lift_kernel<<<444, 256, lsm>>>(l2i, sw1, dw1, db1, sw2, sb2);

    size_t csm = (size_t)SW_ULL * 8 + (size_t)2 * SIN_BUF * 4;  // 129280 B
    cudaFuncSetAttribute(conv_kernel<0>, cudaFuncAttributeMaxDynamicSharedMemorySize, (int)csm);
    cudaFuncSetAttribute(conv_kernel<1>, cudaFuncAttributeMaxDynamicSharedMemorySize, (int)csm);
    conv_kernel<0><<<dim3(5, 10, 24), dim3(32, 8), csm>>>(c1w, b1g, b1b, b1m, b1v, out);
    conv_kernel<1><<<dim3(5, 10, 24), dim3(32, 8), csm>>>(c2w, b2g, b2b, b2m, b2v, out);
}